// round 13
// baseline (speedup 1.0000x reference)
#include <cuda_runtime.h>
#include <cuda_fp16.h>
#include <cstdint>

#define EPSN 1e-12f

constexpr int BATCH = 8;
constexpr int CDIM  = 192;
constexpr int HWSZ  = 16384;   // 128*128
constexpr int NHEAD = 4;
constexpr int CHD   = 48;
constexpr int SPLIT = 8;
constexpr float WSC  = 64.f;
constexpr float IWSC = 1.f / 64.f;

// ---------------------------------------------------------------------------
// helpers
// ---------------------------------------------------------------------------
__device__ __forceinline__ uint32_t s2u(const void* p) {
    uint32_t a;
    asm("{ .reg .u64 t; cvta.to.shared.u64 t, %1; cvt.u32.u64 %0, t; }" : "=r"(a) : "l"(p));
    return a;
}
#define SWZ(x) ((x) ^ (((x) >> 3) & 0x70))

__device__ __forceinline__ void cpa16(uint32_t dst, const void* src, int srcsize) {
    asm volatile("cp.async.cg.shared.global [%0], [%1], 16, %2;"
                 :: "r"(dst), "l"(src), "r"(srcsize));
}
#define CPA_COMMIT() asm volatile("cp.async.commit_group;" ::: "memory")
#define CPA_WAIT(n)  asm volatile("cp.async.wait_group %0;" :: "n"(n) : "memory")

__device__ __forceinline__ void ldsm4(uint32_t* r, uint32_t addr) {
    asm volatile("ldmatrix.sync.aligned.m8n8.x4.shared.b16 {%0,%1,%2,%3}, [%4];"
        : "=r"(r[0]), "=r"(r[1]), "=r"(r[2]), "=r"(r[3]) : "r"(addr));
}
__device__ __forceinline__ void ldsm4t(uint32_t* r, uint32_t addr) {
    asm volatile("ldmatrix.sync.aligned.m8n8.x4.trans.shared.b16 {%0,%1,%2,%3}, [%4];"
        : "=r"(r[0]), "=r"(r[1]), "=r"(r[2]), "=r"(r[3]) : "r"(addr));
}
__device__ __forceinline__ void mma16816h(float* d, const uint32_t* a, const uint32_t* b) {
    asm volatile("mma.sync.aligned.m16n8k16.row.col.f32.f16.f16.f32 "
        "{%0,%1,%2,%3}, {%4,%5,%6,%7}, {%8,%9}, {%0,%1,%2,%3};"
        : "+f"(d[0]), "+f"(d[1]), "+f"(d[2]), "+f"(d[3])
        : "r"(a[0]), "r"(a[1]), "r"(a[2]), "r"(a[3]), "r"(b[0]), "r"(b[1]));
}
__device__ __forceinline__ uint32_t pack2h(__half a, __half b) {
    return (uint32_t)__half_as_ushort(a) | ((uint32_t)__half_as_ushort(b) << 16);
}

// ---------------------------------------------------------------------------
// scratch buffers
// ---------------------------------------------------------------------------
__device__ __half g_wc[256 * 1728];                   // folded 3x3, fp16, x64
__device__ __half g_wq[640 * 192];                    // qkv 1x1 fp16, x64 (1-term)
__device__ __half g_wpb[BATCH * CDIM * CDIM];         // W' = Wp @ attn_b, fp16, x64
__device__ __half g_ch [(size_t)BATCH * CDIM * HWSZ]; // cn fp16 (center)
__device__ __half g_chL[(size_t)BATCH * CDIM * HWSZ];
__device__ __half g_chR[(size_t)BATCH * CDIM * HWSZ];
__device__ __half g_x16[(size_t)BATCH * CDIM * HWSZ]; // x fp16
__device__ __half g_cnf[(size_t)BATCH * CDIM * HWSZ];     // conv out fp16
__device__ __half g_q1h[(size_t)BATCH * 3 * CDIM * HWSZ]; // qkv after 1x1
__device__ __half g_q2h[(size_t)BATCH * 3 * CDIM * HWSZ]; // qkv after dw
__device__ float g_part[(size_t)BATCH * 384 * 8 * 4];     // fused stats partials
__device__ float g_coef[BATCH * CDIM * 3];
__device__ float g_gpart[BATCH * NHEAD * SPLIT * CHD * CHD];
__device__ float g_attn[BATCH * NHEAD * CHD * CHD];

// ---------------------------------------------------------------------------
// weight prep
// ---------------------------------------------------------------------------
__global__ void foldw_kernel(const float* __restrict__ w3, const float* __restrict__ w1,
                             __half* __restrict__ w) {
    int idx = blockIdx.x * 256 + threadIdx.x;          // 256*1728
    int co = idx / 1728, r = idx % 1728;
    int t = r / 192, cj = r % 192;
    float s = 0.f;
    if (co < CDIM)
        for (int ci = 0; ci < CDIM; ci++)
            s = fmaf(w3[(co * CDIM + ci) * 9 + t], w1[ci * CDIM + cj], s);
    w[idx] = __float2half(s * WSC);
}

__global__ void whalf_kernel(const float* __restrict__ w, __half* __restrict__ wo,
                             int validRows) {
    int idx = blockIdx.x * 256 + threadIdx.x;
    int row = idx / CDIM;
    float v = (row < validRows) ? w[(size_t)row * CDIM + (idx % CDIM)] * WSC : 0.f;
    wo[idx] = __float2half(v);
}

__global__ __launch_bounds__(256) void ahalf_kernel(
    const float* __restrict__ in, __half* __restrict__ o, int n4) {
    int i = blockIdx.x * 256 + threadIdx.x;
    if (i >= n4) return;
    float4 v = ((const float4*)in)[i];
    ((uint2*)o)[i] = make_uint2(pack2h(__float2half(v.x), __float2half(v.y)),
                                pack2h(__float2half(v.z), __float2half(v.w)));
}

__global__ __launch_bounds__(256) void asplit_shift_h_kernel(
    const float* __restrict__ in,
    __half* __restrict__ oh, __half* __restrict__ ohL, __half* __restrict__ ohR, int n4) {
    int i = blockIdx.x * 256 + threadIdx.x;
    if (i >= n4) return;
    int p = i * 4;
    int col = p & 127;
    float4 v = ((const float4*)in)[i];
    float vnext = (col == 124) ? 0.f : in[p + 4];
    float vprev = (col == 0)   ? 0.f : in[p - 1];
    __half h0 = __float2half(v.x), h1 = __float2half(v.y);
    __half h2 = __float2half(v.z), h3 = __float2half(v.w);
    __half hn = __float2half(vnext), hp = __float2half(vprev);
    ((uint2*)oh)[i]  = make_uint2(pack2h(h0, h1), pack2h(h2, h3));
    ((uint2*)ohL)[i] = make_uint2(pack2h(h1, h2), pack2h(h3, hn));
    ((uint2*)ohR)[i] = make_uint2(pack2h(hp, h0), pack2h(h1, h2));
}

// ---------------------------------------------------------------------------
// fp16 HMMA GEMM, 1-term, 3-stage cp.async pipeline.
//   CTA tile M=96 x N=128 (8 warps = 2m x 4n; warp tile 48x32), K-chunk 64.
//   bch     : per-batch channel stride of B (CDIM for x/cn, 3*CDIM for v view)
//   wstride : per-batch stride of weights (0 = shared weights)
// ---------------------------------------------------------------------------
template <int KTOT, int TAPS, bool HOUT>
__global__ __launch_bounds__(256, 2) void mm_kernel(
    const __half* __restrict__ xc, const __half* __restrict__ xL,
    const __half* __restrict__ xR,
    const __half* __restrict__ wh,
    void* __restrict__ outv, int Cout, int bch, size_t wstride) {
    constexpr int ATSZ   = 12288;                 // A: 96 rows x 128B
    constexpr int BOFF   = ATSZ;
    constexpr int SSZ    = BOFF + 16384;
    constexpr int STAGES = 3;
    extern __shared__ char sraw[];
    char* sal = (char*)((((uintptr_t)sraw) + 127) & ~(uintptr_t)127);
    const uint32_t sb = s2u(sal);
    const int tid = threadIdx.x, lane = tid & 31, wid = tid >> 5;
    const int n0 = blockIdx.x * 128, m0 = blockIdx.y * 96, b = blockIdx.z;
    const int wm = wid >> 2, wn = wid & 3;        // 2m x 4n warp grid
    const int y = n0 >> 7;
    const int lr = lane & 15, lc = lane >> 4;
    constexpr int NCH = KTOT / 64;
    const __half* wb = wh + (size_t)b * wstride;

    auto load_chunk = [&](int cc) {
        const int k0 = cc * 64;
        const int t = (TAPS == 9) ? (k0 / 192) : 0;
        const int ci0 = k0 - t * 192;
        const int dy = (TAPS == 9) ? (t / 3 - 1) : 0;
        const int dx = (TAPS == 9) ? (t % 3 - 1) : 0;
        const int yy = y + dy;
        const bool rowok = (TAPS == 1) || ((unsigned)yy < 128u);
        const int ys = rowok ? yy : y;
        const uint32_t stg = sb + (uint32_t)(cc % STAGES) * SSZ;
#pragma unroll
        for (int i = 0; i < 3; i++) {
            int e = tid + (i << 8);
            int ck = e & 7, r = e >> 3;
            const __half* src = wb + (size_t)(m0 + r) * KTOT + k0 + ck * 8;
            cpa16(stg + SWZ(r * 128 + ck * 16), src, 16);
        }
        const __half* bp = (dx == 0) ? xc : (dx > 0 ? xL : xR);
        const int sz = rowok ? 16 : 0;
#pragma unroll
        for (int i = 0; i < 4; i++) {
            int e = tid + (i << 8);
            int nc = e & 15, k = (e >> 4) & 63;
            int n = nc * 8;
            const __half* src = bp + ((size_t)b * bch + ci0 + k) * HWSZ + ys * 128 + n;
            cpa16(stg + BOFF + (nc >> 3) * 8192 + SWZ(k * 128 + (n & 63) * 2), src, sz);
        }
        CPA_COMMIT();
    };

    float acc[3][4][4];
#pragma unroll
    for (int i = 0; i < 3; i++)
#pragma unroll
        for (int j = 0; j < 4; j++)
#pragma unroll
            for (int q = 0; q < 4; q++) acc[i][j][q] = 0.f;

#pragma unroll
    for (int i = 0; i < STAGES - 1 && i < NCH; i++) load_chunk(i);

    for (int cc = 0; cc < NCH; cc++) {
        if (cc + STAGES - 1 < NCH) load_chunk(cc + STAGES - 1);
        int pend = ((cc + STAGES - 1 < NCH) ? (STAGES - 1) : (NCH - 1 - cc));
        if (pend >= 2)      CPA_WAIT(2);
        else if (pend == 1) CPA_WAIT(1);
        else                CPA_WAIT(0);
        __syncthreads();
        const uint32_t stg = sb + (uint32_t)(cc % STAGES) * SSZ;

#pragma unroll
        for (int ks = 0; ks < 4; ks++) {
            uint32_t ah[3][4];
#pragma unroll
            for (int mf = 0; mf < 3; mf++)
                ldsm4(ah[mf], stg + SWZ((wm * 48 + mf * 16 + lr) * 128 + ks * 32 + lc * 16));
#pragma unroll
            for (int gg = 0; gg < 2; gg++) {
                int cb = wn * 32 + gg * 16;
                uint32_t bh[4];
                uint32_t bo = BOFF + (cb >> 6) * 8192 +
                              SWZ((ks * 16 + lr) * 128 + (cb & 63) * 2 + lc * 16);
                ldsm4t(bh, stg + bo);
#pragma unroll
                for (int mf = 0; mf < 3; mf++) {
                    mma16816h(acc[mf][2 * gg],     ah[mf], bh);
                    mma16816h(acc[mf][2 * gg + 1], ah[mf], bh + 2);
                }
            }
        }
        __syncthreads();
    }

#pragma unroll
    for (int mf = 0; mf < 3; mf++) {
        int mb = m0 + wm * 48 + mf * 16 + (lane >> 2);
#pragma unroll
        for (int nb = 0; nb < 4; nb++) {
            int nn = n0 + wn * 32 + nb * 8 + (lane & 3) * 2;
            if (HOUT) {
                __half* out = (__half*)outv;
                *(uint32_t*)(out + ((size_t)b * Cout + mb) * HWSZ + nn) =
                    pack2h(__float2half(acc[mf][nb][0] * IWSC),
                           __float2half(acc[mf][nb][1] * IWSC));
                *(uint32_t*)(out + ((size_t)b * Cout + mb + 8) * HWSZ + nn) =
                    pack2h(__float2half(acc[mf][nb][2] * IWSC),
                           __float2half(acc[mf][nb][3] * IWSC));
            } else {
                float* out = (float*)outv;
                *(float2*)(out + ((size_t)b * Cout + mb) * HWSZ + nn) =
                    make_float2(acc[mf][nb][0] * IWSC, acc[mf][nb][1] * IWSC);
                *(float2*)(out + ((size_t)b * Cout + mb + 8) * HWSZ + nn) =
                    make_float2(acc[mf][nb][2] * IWSC, acc[mf][nb][3] * IWSC);
            }
        }
    }
}

// ---------------------------------------------------------------------------
// depthwise 3x3 on fp16 + FUSED norm partials (deterministic, no atomics)
// ---------------------------------------------------------------------------
__global__ __launch_bounds__(256) void dwconv3h_stats_kernel(
    const __half* __restrict__ in, const float* __restrict__ wdw,
    const __half* __restrict__ cnf,
    __half* __restrict__ out, float* __restrict__ part) {
    int c = blockIdx.y, b = blockIdx.z, xb = blockIdx.x;
    int p8 = (xb * 256 + threadIdx.x) * 8;
    int y = p8 >> 7, x = p8 & 127;
    const __half* src = in + ((size_t)b * (3 * CDIM) + c) * HWSZ;
    float w[9];
#pragma unroll
    for (int i = 0; i < 9; i++) w[i] = wdw[c * 9 + i];
    float a[8];
#pragma unroll
    for (int j = 0; j < 8; j++) a[j] = 0.f;
#pragma unroll
    for (int r = -1; r <= 1; r++) {
        int yy = y + r;
        if ((unsigned)yy >= 128u) continue;
        const __half* rp = src + (yy << 7);
        uint4 m4 = *(const uint4*)(rp + x);
        const __half* mh = (const __half*)&m4;
        float v[10];
        v[0] = (x > 0) ? __half2float(rp[x - 1]) : 0.f;
#pragma unroll
        for (int j = 0; j < 8; j++) v[j + 1] = __half2float(mh[j]);
        v[9] = (x + 8 < 128) ? __half2float(rp[x + 8]) : 0.f;
        int wb = (r + 1) * 3;
#pragma unroll
        for (int j = 0; j < 8; j++)
            a[j] = fmaf(w[wb], v[j], fmaf(w[wb + 1], v[j + 1], fmaf(w[wb + 2], v[j + 2], a[j])));
    }
    uint4 o4;
    __half* oh = (__half*)&o4;
#pragma unroll
    for (int j = 0; j < 8; j++) oh[j] = __float2half(a[j]);
    *(uint4*)(out + ((size_t)b * (3 * CDIM) + c) * HWSZ + p8) = o4;

    if (c >= 384) return;
    float s0 = 0.f, s1 = 0.f, s2 = 0.f;
    if (c < CDIM) {
        uint4 c4 = *(const uint4*)(cnf + ((size_t)b * CDIM + c) * HWSZ + p8);
        const __half* chh = (const __half*)&c4;
#pragma unroll
        for (int j = 0; j < 8; j++) {
            float cv = __half2float(chh[j]);
            s0 = fmaf(a[j], a[j], s0);
            s1 = fmaf(cv, cv, s1);
            s2 = fmaf(a[j], cv, s2);
        }
    } else {
#pragma unroll
        for (int j = 0; j < 8; j++) s0 = fmaf(a[j], a[j], s0);
    }
#pragma unroll
    for (int o = 16; o; o >>= 1) {
        s0 += __shfl_xor_sync(~0u, s0, o);
        s1 += __shfl_xor_sync(~0u, s1, o);
        s2 += __shfl_xor_sync(~0u, s2, o);
    }
    __shared__ float rs[3][8];
    int wid = threadIdx.x >> 5, lane = threadIdx.x & 31;
    if (lane == 0) { rs[0][wid] = s0; rs[1][wid] = s1; rs[2][wid] = s2; }
    __syncthreads();
    if (threadIdx.x == 0) {
        float t0 = 0.f, t1 = 0.f, t2 = 0.f;
#pragma unroll
        for (int i = 0; i < 8; i++) { t0 += rs[0][i]; t1 += rs[1][i]; t2 += rs[2][i]; }
        ((float4*)part)[((size_t)b * 384 + c) * 8 + xb] = make_float4(t0, t1, t2, 0.f);
    }
}

__global__ __launch_bounds__(256) void coef_kernel(
    const float* __restrict__ part, float* __restrict__ coef) {
    int row = blockIdx.x * 256 + threadIdx.x;
    if (row >= BATCH * CDIM) return;
    int b = row / CDIM, c = row % CDIM;
    const float4* pq = (const float4*)part + ((size_t)b * 384 + c) * 8;
    const float4* pk = (const float4*)part + ((size_t)b * 384 + CDIM + c) * 8;
    float SQ = 0.f, SC = 0.f, SQC = 0.f, SK = 0.f;
#pragma unroll
    for (int i = 0; i < 8; i++) {
        float4 q = pq[i];
        SQ += q.x; SC += q.y; SQC += q.z;
        SK += pk[i].x;
    }
    float a  = fmaxf(sqrtf(SQ), EPSN);
    float bb = fmaxf(sqrtf(SC), EPSN);
    float s2 = SQ / (a * a) + 2.f * SQC / (a * bb) + SC / (bb * bb);
    float s  = fmaxf(sqrtf(s2), EPSN);
    float kn = fmaxf(sqrtf(SK), EPSN);
    coef[row * 3 + 0] = 1.f / (a * s);
    coef[row * 3 + 1] = 1.f / (bb * s);
    coef[row * 3 + 2] = 1.f / kn;
}

// ---------------------------------------------------------------------------
// gram via HMMA (unchanged)
// ---------------------------------------------------------------------------
__global__ __launch_bounds__(256) void gram_mma_kernel(
    const __half* __restrict__ qkv, const __half* __restrict__ cnf,
    const float* __restrict__ coef, float* __restrict__ gpart) {
    __shared__ __align__(16) char QS[8192];
    __shared__ __align__(16) char KS[8192];
    __shared__ float al[48], be[48], ga[48];
    int bh = blockIdx.x, sp = blockIdx.y;
    int b = bh >> 2, h = bh & 3;
    int tid = threadIdx.x, lane = tid & 31, wid = tid >> 5;
    int wm = wid >> 1, wn = wid & 1;
    int lr = lane & 15, lc = lane >> 4;
    uint32_t qs = s2u(QS), ksm = s2u(KS);
    if (tid < 48) {
        int rw = b * CDIM + h * CHD + tid;
        al[tid] = coef[rw * 3 + 0]; be[tid] = coef[rw * 3 + 1]; ga[tid] = coef[rw * 3 + 2];
    }
    const __half* qb = qkv + ((size_t)b * (3 * CDIM) + h * CHD) * HWSZ;
    const __half* kb = qkv + ((size_t)b * (3 * CDIM) + CDIM + h * CHD) * HWSZ;
    const __half* cb = cnf + ((size_t)b * CDIM + h * CHD) * HWSZ;
    float acc[4][4] = {};
    __syncthreads();
    int send = sp * 2048 + 2048;
    for (int s0 = sp * 2048; s0 < send; s0 += 64) {
        for (int e = tid; e < 1536; e += 256) {
            int r = e >> 5, sc = (e & 31) * 2;
            size_t off = (size_t)r * HWSZ + s0 + sc;
            float2 q2 = __half22float2(*(const __half2*)(qb + off));
            float2 c2 = __half22float2(*(const __half2*)(cb + off));
            *(uint32_t*)(QS + SWZ(r * 128 + sc * 2)) =
                pack2h(__float2half(al[r] * q2.x + be[r] * c2.x),
                       __float2half(al[r] * q2.y + be[r] * c2.y));
            float2 k2 = __half22float2(*(const __half2*)(kb + off));
            *(__half*)(KS + SWZ(sc * 128 + r * 2))       = __float2half(ga[r] * k2.x);
            *(__half*)(KS + SWZ((sc + 1) * 128 + r * 2)) = __float2half(ga[r] * k2.y);
        }
        __syncthreads();
#pragma unroll
        for (int ks = 0; ks < 4; ks++) {
            uint32_t af[4];
            ldsm4(af, qs + SWZ((wm * 16 + lr) * 128 + ks * 32 + lc * 16));
#pragma unroll
            for (int g = 0; g < 2; g++) {
                uint32_t bf[4];
                ldsm4t(bf, ksm + SWZ((ks * 16 + lr) * 128 + (wn * 32 + g * 16) * 2 + lc * 16));
                mma16816h(acc[2 * g],     af, bf);
                mma16816h(acc[2 * g + 1], af, bf + 2);
            }
        }
        __syncthreads();
    }
    if (wm < 3) {
        int c = wm * 16 + (lane >> 2);
#pragma unroll
        for (int nb = 0; nb < 4; nb++) {
            int d0 = wn * 32 + nb * 8;
            if (d0 < 48) {
                int dd = d0 + (lane & 3) * 2;
                float* g0 = gpart + ((size_t)(bh * SPLIT + sp) * CHD + c) * CHD + dd;
                g0[0] = acc[nb][0]; g0[1] = acc[nb][1];
                float* g1 = gpart + ((size_t)(bh * SPLIT + sp) * CHD + c + 8) * CHD + dd;
                g1[0] = acc[nb][2]; g1[1] = acc[nb][3];
            }
        }
    }
}

__global__ __launch_bounds__(256) void softmax_kernel(
    const float* __restrict__ gpart, const float* __restrict__ temp,
    float* __restrict__ attn) {
    __shared__ float S[48][49];
    int bh = blockIdx.x;
    float T = temp[bh & 3];
    int tid = threadIdx.x;
    for (int e = tid; e < CHD * CHD; e += 256) {
        int c = e / CHD, d = e - c * CHD;
        float g = 0.f;
#pragma unroll
        for (int sp = 0; sp < SPLIT; sp++)
            g += gpart[((bh * SPLIT + sp) * CHD + c) * CHD + d];
        S[c][d] = g * T;
    }
    __syncthreads();
    int wid = tid >> 5, lane = tid & 31;
    for (int r = wid; r < 48; r += 8) {
        float v1 = S[r][lane];
        float v2 = (lane < 16) ? S[r][32 + lane] : -1e30f;
        float m = fmaxf(v1, v2);
#pragma unroll
        for (int o = 16; o; o >>= 1) m = fmaxf(m, __shfl_xor_sync(~0u, m, o));
        float e1 = expf(v1 - m);
        float e2 = (lane < 16) ? expf(v2 - m) : 0.f;
        float s = e1 + e2;
#pragma unroll
        for (int o = 16; o; o >>= 1) s += __shfl_xor_sync(~0u, s, o);
        float inv = 1.f / s;
        attn[bh * (CHD * CHD) + r * CHD + lane] = e1 * inv;
        if (lane < 16) attn[bh * (CHD * CHD) + r * CHD + 32 + lane] = e2 * inv;
    }
}

// ---------------------------------------------------------------------------
// W'[b] = Wp @ blockdiag(attn_b), per-head block: Wp[:,h*48:(h+1)*48] @ attn_h
//   one CTA per batch; attn in smem; output fp16 x64 [192][192]
// ---------------------------------------------------------------------------
__global__ __launch_bounds__(256) void wprime_kernel(
    const float* __restrict__ projw, const float* __restrict__ attn,
    __half* __restrict__ wpb) {
    __shared__ float A[NHEAD][CHD][CHD];
    int b = blockIdx.x, tid = threadIdx.x;
    const float* ab = attn + (size_t)b * NHEAD * CHD * CHD;
    for (int e = tid; e < NHEAD * CHD * CHD; e += 256)
        ((float*)A)[e] = ab[e];
    __syncthreads();
    // each thread computes outputs e = co*192 + (h*48+d), strided
    for (int e = tid; e < CDIM * CDIM; e += 256) {
        int co = e / CDIM, k = e % CDIM;
        int h = k / CHD, d = k % CHD;
        const float* wrow = projw + (size_t)co * CDIM + h * CHD;
        float s = 0.f;
#pragma unroll 8
        for (int cp = 0; cp < CHD; cp++)
            s = fmaf(wrow[cp], A[h][cp][d], s);
        wpb[(size_t)b * CDIM * CDIM + e] = __float2half(s * WSC);
    }
}

// ---------------------------------------------------------------------------
// launch
// ---------------------------------------------------------------------------
constexpr int SMEM_1T = 3 * 28672 + 128;   // 3 stages x 28KB, 2 CTAs/SM

extern "C" void kernel_launch(void* const* d_in, const int* in_sizes, int n_in,
                              void* d_out, int out_size) {
    const float* x     = (const float*)d_in[0];
    const float* cn    = (const float*)d_in[1];
    const float* w1    = (const float*)d_in[2];
    const float* w3    = (const float*)d_in[3];
    const float* qkvw  = (const float*)d_in[4];
    const float* dww   = (const float*)d_in[5];
    const float* projw = (const float*)d_in[6];
    const float* temp  = (const float*)d_in[7];

    __half *wc, *wq, *wpb, *ch, *chL, *chR, *x16, *cnf, *q1h, *q2h;
    float *part, *coef, *gpart, *attn;
    cudaGetSymbolAddress((void**)&wc,  g_wc);
    cudaGetSymbolAddress((void**)&wq,  g_wq);
    cudaGetSymbolAddress((void**)&wpb, g_wpb);
    cudaGetSymbolAddress((void**)&ch,  g_ch);
    cudaGetSymbolAddress((void**)&chL, g_chL);
    cudaGetSymbolAddress((void**)&chR, g_chR);
    cudaGetSymbolAddress((void**)&x16, g_x16);
    cudaGetSymbolAddress((void**)&cnf, g_cnf);
    cudaGetSymbolAddress((void**)&q1h, g_q1h);
    cudaGetSymbolAddress((void**)&q2h, g_q2h);
    cudaGetSymbolAddress((void**)&part, g_part);
    cudaGetSymbolAddress((void**)&coef, g_coef);
    cudaGetSymbolAddress((void**)&gpart, g_gpart);
    cudaGetSymbolAddress((void**)&attn, g_attn);

    cudaFuncSetAttribute(mm_kernel<1728, 9, true>,
                         cudaFuncAttributeMaxDynamicSharedMemorySize, SMEM_1T);
    cudaFuncSetAttribute(mm_kernel<192, 1, true>,
                         cudaFuncAttributeMaxDynamicSharedMemorySize, SMEM_1T);
    cudaFuncSetAttribute(mm_kernel<192, 1, false>,
                         cudaFuncAttributeMaxDynamicSharedMemorySize, SMEM_1T);

    const int NACT4 = BATCH * CDIM * HWSZ / 4;

    // weight prep
    foldw_kernel<<<256 * 1728 / 256, 256>>>(w3, w1, wc);
    whalf_kernel<<<640 * 192 / 256, 256>>>(qkvw, wq, 3 * CDIM);

    // cn branch: fp16 + shifted copies, folded 3x3 conv -> fp16 cnf
    asplit_shift_h_kernel<<<(NACT4 + 255) / 256, 256>>>(cn, ch, chL, chR, NACT4);
    mm_kernel<1728, 9, true><<<dim3(128, 2, BATCH), 256, SMEM_1T>>>(
        ch, chL, chR, wc, cnf, CDIM, CDIM, 0);

    // qkv 1x1: single 1-term launch (q,k,v)
    ahalf_kernel<<<(NACT4 + 255) / 256, 256>>>(x, x16, NACT4);
    mm_kernel<192, 1, true><<<dim3(128, 6, BATCH), 256, SMEM_1T>>>(
        x16, x16, x16, wq, q1h, 3 * CDIM, CDIM, 0);

    // depthwise 3x3 + fused norm partials
    dwconv3h_stats_kernel<<<dim3(HWSZ / 2048, 3 * CDIM, BATCH), 256>>>(
        q1h, dww, cnf, q2h, part);
    coef_kernel<<<(BATCH * CDIM + 255) / 256, 256>>>(part, coef);

    // attention: gram -> softmax -> fold attn into projection weights
    gram_mma_kernel<<<dim3(BATCH * NHEAD, SPLIT), 256>>>(q2h, cnf, coef, gpart);
    softmax_kernel<<<BATCH * NHEAD, 256>>>(gpart, temp, attn);
    wprime_kernel<<<BATCH, 256>>>(projw, attn, wpb);

    // fused projection: out = W'_b @ v  (reads v rows of q2h directly)
    mm_kernel<192, 1, false><<<dim3(128, 2, BATCH), 256, SMEM_1T>>>(
        q2h + (size_t)2 * CDIM * HWSZ, q2h, q2h, wpb,
        (float*)d_out, CDIM, 3 * CDIM, (size_t)CDIM * CDIM);
}